// round 15
// baseline (speedup 1.0000x reference)
#include <cuda_runtime.h>
#include <cuda_bf16.h>

#define NB 16
#define NA 49104
#define PRE_CAP 6144
#define PRE_BITS 0x3F700000u   // 0.9375f ; all prelist items have (bits>>20) >= 0x3F7

// ---------------- scratch (device globals) ----------------
__device__ float g_score[NB * NA];
__device__ unsigned char g_clsArg[NB * NA];
__device__ int   g_pcnt[NB];
__device__ int   g_pover[NB];
__device__ int   g_cnt[NB];
__device__ unsigned long long g_pre[NB * PRE_CAP];
__device__ unsigned long long g_cand[NB * 1024];

__device__ float g_topScore[NB * 1024];
__device__ float g_topCls[NB * 1024];
__device__ float g_topTheta[NB * 1024];
__device__ float g_topBox[NB * 1024 * 4];

__device__ unsigned g_W[NB * 32 * 1024];  // [b][g][j] : bit i = iou(i,j)>thr  (only wid>g region written/read)
__device__ unsigned g_U[NB * 1024];       // [b][g*32+i] : intra-group row (suppressor i)

struct Ptrs { const float* p[20]; };

__device__ __forceinline__ void level_of(int a, int& l, int& p, int& h, int& s) {
    if (a < 36864)      { l = 0; p = a;         h = 192; s = 8;   }
    else if (a < 46080) { l = 1; p = a - 36864; h = 96;  s = 16;  }
    else if (a < 48384) { l = 2; p = a - 46080; h = 48;  s = 32;  }
    else if (a < 48960) { l = 3; p = a - 48384; h = 24;  s = 64;  }
    else                { l = 4; p = a - 48960; h = 12;  s = 128; }
}

// ---------------- kernel 0: zero counters ----------------
__global__ void zero_kernel() {
    int t = threadIdx.x;
    if (t < NB) { g_pcnt[t] = 0; g_pover[t] = 0; }
}

// ---------------- kernel 1: scores + cls argmax + prelist ----------------
__global__ void __launch_bounds__(256) score_pre_kernel(Ptrs in) {
    __shared__ int wtot[8];
    __shared__ int sBase;
    int b = blockIdx.y, bx = blockIdx.x, tid = threadIdx.x;
    int lane = tid & 31, wd = tid >> 5;

    int base = bx * 2048 + tid * 8;   // 8 anchors / thread; 4-groups never cross level bound
    unsigned kb[8];
    int cntP = 0;
    bool act = base < NA;
    if (act) {
#pragma unroll
        for (int q = 0; q < 2; q++) {
            int a0 = base + q * 4;
            int l, p, h, s; level_of(a0, l, p, h, s);
            int hh = h * h;
            const float4* cls = (const float4*)(in.p[l] + b * 15 * hh + p);
            int st = hh >> 2;
            float4 m4 = cls[0];
            int ax = 0, ay = 0, az = 0, aw = 0;
#pragma unroll
            for (int c = 1; c < 15; c++) {
                float4 v = cls[c * st];
                if (v.x > m4.x) { m4.x = v.x; ax = c; }
                if (v.y > m4.y) { m4.y = v.y; ay = c; }
                if (v.z > m4.z) { m4.z = v.z; az = c; }
                if (v.w > m4.w) { m4.w = v.w; aw = c; }
            }
            float4 sc;
            sc.x = 1.0f / (1.0f + expf(-m4.x));
            sc.y = 1.0f / (1.0f + expf(-m4.y));
            sc.z = 1.0f / (1.0f + expf(-m4.z));
            sc.w = 1.0f / (1.0f + expf(-m4.w));
            *(float4*)&g_score[b * NA + a0] = sc;
            *(uchar4*)&g_clsArg[b * NA + a0] =
                make_uchar4((unsigned char)ax, (unsigned char)ay,
                            (unsigned char)az, (unsigned char)aw);
            kb[q * 4 + 0] = __float_as_uint(sc.x);
            kb[q * 4 + 1] = __float_as_uint(sc.y);
            kb[q * 4 + 2] = __float_as_uint(sc.z);
            kb[q * 4 + 3] = __float_as_uint(sc.w);
        }
#pragma unroll
        for (int q = 0; q < 8; q++) cntP += (kb[q] >= PRE_BITS);
    }
    int inc = cntP;
#pragma unroll
    for (int d = 1; d < 32; d <<= 1) {
        int t = __shfl_up_sync(0xffffffffu, inc, d);
        if (lane >= d) inc += t;
    }
    if (lane == 31) wtot[wd] = inc;
    __syncthreads();
    if (tid == 0) {
        int tot = 0;
#pragma unroll
        for (int w = 0; w < 8; w++) { int t = wtot[w]; wtot[w] = tot; tot += t; }
        sBase = tot ? atomicAdd(&g_pcnt[b], tot) : 0;
    }
    __syncthreads();
    if (act && cntP) {
        int off = sBase + wtot[wd] + (inc - cntP);
#pragma unroll
        for (int q = 0; q < 8; q++) {
            if (kb[q] >= PRE_BITS) {
                if (off < PRE_CAP)
                    g_pre[b * PRE_CAP + off] = ((unsigned long long)kb[q] << 32) | (unsigned)(base + q);
                else
                    g_pover[b] = 1;
                off++;
            }
        }
    }
}

// ---------------- threshold finder over a shared histogram ----------------
__device__ __forceinline__ void find_thresh(const int* h, int nbins, int target,
                                            int* partial, int* res, int tid,
                                            int& T, int& acc) {
    int spb = nbins >> 8;
    if (tid < 256) { int s = 0; for (int i = 0; i < spb; i++) s += h[tid * spb + i]; partial[tid] = s; }
    __syncthreads();
    if (tid == 0) {
        int a = 0, TT = 0;
        for (int seg = 255; seg >= 0; seg--) {
            int ps = partial[seg];
            if (a + ps >= target) {
                for (int bin = seg * spb + spb - 1;; bin--) {
                    int hc = h[bin];
                    if (a + hc >= target) { TT = bin; break; }
                    a += hc;
                }
                break;
            }
            a += ps;
        }
        res[0] = TT; res[1] = a;
    }
    __syncthreads();
    T = res[0]; acc = res[1];
}

// ---------------- ballot-aggregated emit into shared cand ----------------
__device__ __forceinline__ void emit_sh(bool em, unsigned k, unsigned a,
                                        unsigned long long* cand, int* sCnt, int lane) {
    unsigned mv = __ballot_sync(0xffffffffu, em);
    if (mv) {
        int ldr = __ffs(mv) - 1;
        int pos = 0;
        if (lane == ldr) pos = atomicAdd(sCnt, __popc(mv));
        pos = __shfl_sync(0xffffffffu, pos, ldr);
        if (em) {
            int o = pos + __popc(mv & ((1u << lane) - 1));
            if (o < 1024)
                cand[o] = ((unsigned long long)(~k) << 32) | a;  // asc sort = desc score, asc idx
        }
    }
}

// ---------------- kernel 2: select + sort (per batch) ----------------
__global__ void __launch_bounds__(1024) topk_kernel() {
    __shared__ int h[4096];
    __shared__ int partial[256];
    __shared__ int res[2];
    __shared__ int h3[256];
    __shared__ int sCnt, sHi;
    __shared__ unsigned long long cand[1024];
    int b = blockIdx.x, tid = threadIdx.x, lane = tid & 31;

    int pcnt = min(g_pcnt[b], PRE_CAP);
    bool usable = (pcnt >= 1000) && (g_pover[b] == 0);
    const unsigned long long* pre = g_pre + b * PRE_CAP;
    const float* sc = g_score + b * NA;

    for (int i = tid; i < 4096; i += 1024) h[i] = 0;
    if (tid < 256) h3[tid] = 0;
    if (tid == 0) { sCnt = 0; sHi = 0; }
    __syncthreads();

    // ---- stage 0: determine T1 / acc1 ----
    int T1, acc1;
    if (usable) {
        int c = 0;
        for (int i = tid; i < pcnt; i += 1024)
            c += ((unsigned)(pre[i] >> 32) >= 0x3F800000u);
#pragma unroll
        for (int d = 16; d > 0; d >>= 1) c += __shfl_down_sync(0xffffffffu, c, d);
        if (lane == 0 && c) atomicAdd(&sHi, c);
    }
    __syncthreads();
    if (usable && sHi < 1000) {
        T1 = 0x3F7; acc1 = sHi;
    } else {
        usable = false;
        for (int it = 0; it < 48; it++) {
            int i = it * 1024 + tid;
            bool v = i < NA;
            unsigned bal = __ballot_sync(0xffffffffu, v);
            if (v) {
                int bin = (int)(__float_as_uint(sc[i]) >> 20);
                unsigned mm = __match_any_sync(bal, bin);
                if (lane == (int)(__ffs(mm) - 1)) atomicAdd(&h[bin], __popc(mm));
            }
        }
        __syncthreads();
        find_thresh(h, 4096, 1000, partial, res, tid, T1, acc1);
        __syncthreads();
        for (int i = tid; i < 4096; i += 1024) h[i] = 0;
        __syncthreads();
    }

    int nIt = usable ? ((pcnt + 1023) >> 10) : 48;

    // ---- stage 1: emit bin>T1 ; hist mid-12 for bin==T1 ----
    for (int it = 0; it < nIt; it++) {
        int i = it * 1024 + tid;
        unsigned k = 0, a = 0; bool em = false;
        if (usable) {
            if (i < pcnt) { unsigned long long v = pre[i]; k = (unsigned)(v >> 32); a = (unsigned)v; }
        } else if (i < NA) { k = __float_as_uint(sc[i]); a = (unsigned)i; }
        if (k) {
            int bin = (int)(k >> 20);
            if (bin > T1) em = true;
            else if (bin == T1) atomicAdd(&h[(k >> 8) & 0xFFF], 1);
        }
        emit_sh(em, k, a, cand, &sCnt, lane);
    }
    __syncthreads();
    int T2, acc2;
    find_thresh(h, 4096, 1000 - acc1, partial, res, tid, T2, acc2);
    __syncthreads();

    // ---- stage 2: low-byte hist for bin==T1 && mid==T2 ----
    for (int it = 0; it < nIt; it++) {
        int i = it * 1024 + tid;
        unsigned k = 0;
        if (usable) { if (i < pcnt) k = (unsigned)(pre[i] >> 32); }
        else if (i < NA) k = __float_as_uint(sc[i]);
        if (k && (int)(k >> 20) == T1 && (int)((k >> 8) & 0xFFF) == T2)
            atomicAdd(&h3[k & 0xFF], 1);
    }
    __syncthreads();
    if (tid == 0) {
        int tg = 1000 - acc1 - acc2, a = 0, T = 0;
        for (int bin = 255;; bin--) {
            int hc = h3[bin];
            if (a + hc >= tg) { T = bin; break; }
            a += hc;
        }
        res[0] = T;
    }
    __syncthreads();
    int T3 = res[0];

    // ---- stage 3: emit remainder ----
    for (int it = 0; it < nIt; it++) {
        int i = it * 1024 + tid;
        unsigned k = 0, a = 0; bool em = false;
        if (usable) {
            if (i < pcnt) { unsigned long long v = pre[i]; k = (unsigned)(v >> 32); a = (unsigned)v; }
        } else if (i < NA) { k = __float_as_uint(sc[i]); a = (unsigned)i; }
        if (k && (int)(k >> 20) == T1) {
            int mid = (int)((k >> 8) & 0xFFF);
            em = (mid > T2) || (mid == T2 && (int)(k & 0xFF) >= T3);
        }
        emit_sh(em, k, a, cand, &sCnt, lane);
    }
    __syncthreads();
    int c = min(sCnt, 1024);
    if (tid >= c) cand[tid] = 0xFFFFFFFFFFFFFFFFULL;
    __syncthreads();

    // ---- stage 4: bitonic sort 1024 ascending ----
    for (int k2 = 2; k2 <= 32; k2 <<= 1) {
        for (int s2 = k2 >> 1; s2 > 0; s2 >>= 1) {
            __syncwarp();
            int q = tid ^ s2;
            if (q > tid) {
                bool asc = ((tid & k2) == 0);
                unsigned long long A = cand[tid], Bv = cand[q];
                if ((A > Bv) == asc) { cand[tid] = Bv; cand[q] = A; }
            }
        }
    }
    for (int k2 = 64; k2 <= 1024; k2 <<= 1) {
        for (int s2 = k2 >> 1; s2 > 0; s2 >>= 1) {
            if (s2 >= 16) __syncthreads(); else __syncwarp();
            int q = tid ^ s2;
            if (q > tid) {
                bool asc = ((tid & k2) == 0);
                unsigned long long A = cand[tid], Bv = cand[q];
                if ((A > Bv) == asc) { cand[tid] = Bv; cand[q] = A; }
            }
        }
    }
    __syncthreads();
    g_cand[b * 1024 + tid] = cand[tid];
    if (tid == 0) g_cnt[b] = c;
}

// ---------------- kernel 3: winner decode — one WARP per winner, cls argmax precomputed ----------------
__global__ void __launch_bounds__(256) decode_kernel(Ptrs in) {
    int b = blockIdx.y;
    int w = blockIdx.x * 8 + (threadIdx.x >> 5);   // winner slot 0..1023
    int lane = threadIdx.x & 31;
    int o = b * 1024 + w;
    int cnt = g_cnt[b];

    if (w < 1000 && w < cnt) {
        unsigned long long v = g_cand[o];
        int a = (int)(unsigned)(v & 0xFFFFFFFFu);
        float score = __uint_as_float(~(unsigned)(v >> 32));

        int l, p, h2, s; level_of(a, l, p, h2, s);
        int hh = h2 * h2;
        const float* reg = in.p[5 + l]  + b * 5  * hh + p;
        const float* tcp = in.p[10 + l] + b * 18 * hh + p;
        const float* trp = in.p[15 + l] + b * hh + p;

        // parallel channel loads (1 per lane), then shuffle argmax (tie -> lower idx)
        float v2 = (lane < 18) ? tcp[lane * hh] : -1e30f;
        int   i2 = lane;
        float rq = (lane < 4) ? reg[lane * hh] : ((lane == 4) ? trp[0] : 0.f);
        int clsA = (lane == 5) ? (int)g_clsArg[b * NA + a] : 0;
#pragma unroll
        for (int d = 16; d > 0; d >>= 1) {
            float ov2 = __shfl_down_sync(0xffffffffu, v2, d);
            int   oi2 = __shfl_down_sync(0xffffffffu, i2, d);
            if (ov2 > v2 || (ov2 == v2 && oi2 < i2)) { v2 = ov2; i2 = oi2; }
        }
        float r0v = __shfl_sync(0xffffffffu, rq, 0);
        float r1v = __shfl_sync(0xffffffffu, rq, 1);
        float r2v = __shfl_sync(0xffffffffu, rq, 2);
        float r3v = __shfl_sync(0xffffffffu, rq, 3);
        float trv = __shfl_sync(0xffffffffu, rq, 4);
        clsA = __shfl_sync(0xffffffffu, clsA, 5);

        if (lane == 0) {
            float theta = (float)(i2 + 1) * 10.0f + trv;
            float fs = (float)s;
            int col = p % h2, row = p / h2;
            float x = (float)col * fs + (float)(s / 2);
            float y = (float)row * fs + (float)(s / 2);

            g_topScore[o] = score;
            g_topCls[o]   = (float)(clsA + 1);
            g_topTheta[o] = theta;
            g_topBox[o * 4 + 0] = x - r0v * fs;
            g_topBox[o * 4 + 1] = y - r1v * fs;
            g_topBox[o * 4 + 2] = x + r2v * fs;
            g_topBox[o * 4 + 3] = y + r3v * fs;
        }
    } else if (lane == 0) {
        g_topScore[o] = -1e30f;
        g_topCls[o] = 0.f; g_topTheta[o] = 0.f;
        g_topBox[o * 4 + 0] = 0.f; g_topBox[o * 4 + 1] = 0.f;
        g_topBox[o * 4 + 2] = 0.f; g_topBox[o * 4 + 3] = 0.f;
    }
}

// ---------------- kernel 4: IoU bit-masks (slimmed inner loop) ----------------
__global__ void __launch_bounds__(1024) mask_kernel() {
    int b = blockIdx.y, g = blockIdx.x, j = threadIdx.x;
    int wid = j >> 5, lane = j & 31;
    __shared__ float ib[32][5];     // x1,y1,x2,y2,area (stride 5: conflict-free broadcast)
    if (j < 32) {
        float x1 = g_topBox[(b * 1024 + g * 32 + j) * 4 + 0];
        float y1 = g_topBox[(b * 1024 + g * 32 + j) * 4 + 1];
        float x2 = g_topBox[(b * 1024 + g * 32 + j) * 4 + 2];
        float y2 = g_topBox[(b * 1024 + g * 32 + j) * 4 + 3];
        ib[j][0] = x1; ib[j][1] = y1; ib[j][2] = x2; ib[j][3] = y2;
        ib[j][4] = fmaxf(x2 - x1, 0.f) * fmaxf(y2 - y1, 0.f);
    }
    __syncthreads();

    if (wid < g) return;   // dead region: scan never reads these words

    float x1 = g_topBox[(b * 1024 + j) * 4 + 0];
    float y1 = g_topBox[(b * 1024 + j) * 4 + 1];
    float x2 = g_topBox[(b * 1024 + j) * 4 + 2];
    float y2 = g_topBox[(b * 1024 + j) * 4 + 3];
    float area = fmaxf(x2 - x1, 0.f) * fmaxf(y2 - y1, 0.f);

    if (wid > g) {
        unsigned w = 0;
#pragma unroll
        for (int bb = 0; bb < 32; bb++) {
            float iw = fmaxf(fminf(x2, ib[bb][2]) - fmaxf(x1, ib[bb][0]), 0.f);
            float ih = fmaxf(fminf(y2, ib[bb][3]) - fmaxf(y1, ib[bb][1]), 0.f);
            float inter = iw * ih;
            float uni = fmaxf(area + ib[bb][4] - inter, 1e-8f);
            w |= ((unsigned)(inter > 0.3f * uni)) << bb;
        }
        g_W[(b * 32 + g) * 1024 + j] = w;
    } else {
        unsigned w = 0;
#pragma unroll
        for (int bb = 0; bb < 32; bb++) {
            float iw = fmaxf(fminf(x2, ib[bb][2]) - fmaxf(x1, ib[bb][0]), 0.f);
            float ih = fmaxf(fminf(y2, ib[bb][3]) - fmaxf(y1, ib[bb][1]), 0.f);
            float inter = iw * ih;
            float uni = fmaxf(area + ib[bb][4] - inter, 1e-8f);
            bool pred = (inter > 0.3f * uni) && (bb < lane);
            w |= ((unsigned)pred) << bb;
        }
        unsigned u = 0;
#pragma unroll
        for (int i = 0; i < 32; i++) {
            unsigned t = __ballot_sync(0xffffffffu, (w >> i) & 1u);
            if (lane == i) u = t;
        }
        g_U[b * 1024 + g * 32 + lane] = u;
    }
}

// ---------------- kernel 5: barrier-free pipelined greedy scan + output ----------------
__global__ void __launch_bounds__(1024) scan_kernel(float* __restrict__ out) {
    int b = blockIdx.x, j = threadIdx.x;
    int lane = j & 31, wid = j >> 5;
    __shared__ unsigned su[1024];
    __shared__ unsigned long long sm64[32];

    float score = g_topScore[b * 1024 + j];
    bool alive = (j < 1000) && (score >= 0.05f);

    unsigned su_own = g_U[b * 1024 + j];
    su[j] = su_own;
    if (j < 32) sm64[j] = 0ULL;
    unsigned nzm = __ballot_sync(0xffffffffu, su_own != 0u);
    __syncthreads();

    const unsigned* Wb = g_W + b * 32 * 1024;
    for (int g = 0; g < wid; g++) {
        unsigned wv = Wb[g * 1024 + j];
        unsigned long long v;
        do { v = *(volatile const unsigned long long*)&sm64[g]; } while (!(v >> 32));
        unsigned mg = (unsigned)v;
        alive = alive && ((wv & mg) == 0u);
    }
    unsigned m = __ballot_sync(0xffffffffu, alive);
    if (lane == 0) {
        unsigned todo = nzm & m;
        while (todo) {
            int bb = __ffs(todo) - 1;
            m &= ~su[wid * 32 + bb];
            todo &= todo - 1;
            todo &= m;
        }
        *(volatile unsigned long long*)&sm64[wid] = (1ULL << 32) | (unsigned long long)m;
    }
    m = __shfl_sync(0xffffffffu, m, 0);
    alive = (m >> lane) & 1u;

    if (j < 1000) {
        float k = alive ? 1.0f : 0.0f;
        int o = b * 1024 + j;
        out[b * 1000 + j] = score * k;
        out[16000 + b * 1000 + j] = k * g_topCls[o];
        int base = 32000 + (b * 1000 + j) * 5;
        out[base + 0] = k * g_topBox[o * 4 + 0];
        out[base + 1] = k * g_topBox[o * 4 + 1];
        out[base + 2] = k * g_topBox[o * 4 + 2];
        out[base + 3] = k * g_topBox[o * 4 + 3];
        out[base + 4] = k * g_topTheta[o];
    }
}

// ---------------- launch ----------------
extern "C" void kernel_launch(void* const* d_in, const int* in_sizes, int n_in,
                              void* d_out, int out_size) {
    Ptrs P;
    for (int i = 0; i < 20; i++) P.p[i] = (const float*)d_in[i];

    zero_kernel<<<1, 32>>>();
    score_pre_kernel<<<dim3(24, NB), 256>>>(P);
    topk_kernel<<<NB, 1024>>>();
    decode_kernel<<<dim3(128, NB), 256>>>(P);
    mask_kernel<<<dim3(32, NB), 1024>>>();
    scan_kernel<<<NB, 1024>>>((float*)d_out);
}

// round 16
// speedup vs baseline: 1.0303x; 1.0303x over previous
#include <cuda_runtime.h>
#include <cuda_bf16.h>

#define NB 16
#define NA 49104
#define PRE_CAP 6144
#define PRE_BITS 0x3F700000u   // 0.9375f ; all prelist items have (bits>>20) >= 0x3F7

// ---------------- scratch (device globals; zero-initialized at module load) ----------------
__device__ float g_score[NB * NA];
__device__ unsigned char g_clsArg[NB * NA];   // written only for prelist anchors
__device__ int   g_pcnt[NB];
__device__ int   g_pover[NB];
__device__ int   g_cnt[NB];
__device__ int   g_usable[NB];
__device__ unsigned long long g_pre[NB * PRE_CAP];
__device__ unsigned long long g_cand[NB * 1024];

__device__ float g_topScore[NB * 1024];
__device__ float g_topCls[NB * 1024];
__device__ float g_topTheta[NB * 1024];
__device__ float g_topBox[NB * 1024 * 4];

__device__ unsigned g_W[NB * 32 * 1024];  // [b][g][j] : bit i = iou(i,j)>thr  (only wid>g region)
__device__ unsigned g_U[NB * 1024];       // [b][g*32+i] : intra-group row (suppressor i)

struct Ptrs { const float* p[20]; };

__device__ __forceinline__ void level_of(int a, int& l, int& p, int& h, int& s) {
    if (a < 36864)      { l = 0; p = a;         h = 192; s = 8;   }
    else if (a < 46080) { l = 1; p = a - 36864; h = 96;  s = 16;  }
    else if (a < 48384) { l = 2; p = a - 46080; h = 48;  s = 32;  }
    else if (a < 48960) { l = 3; p = a - 48384; h = 24;  s = 64;  }
    else                { l = 4; p = a - 48960; h = 12;  s = 128; }
}

// ---------------- kernel 1: scores (fmaxf only) + prelist + hot-argmax for prelist anchors ----------------
__global__ void __launch_bounds__(256) score_pre_kernel(Ptrs in) {
    __shared__ int wtot[8];
    __shared__ int sBase;
    int b = blockIdx.y, bx = blockIdx.x, tid = threadIdx.x;
    int lane = tid & 31, wd = tid >> 5;

    int base = bx * 2048 + tid * 8;   // 8 anchors / thread; 4-groups never cross level bound
    unsigned kb[8];
    int cntP = 0;
    bool act = base < NA;
    if (act) {
#pragma unroll
        for (int q = 0; q < 2; q++) {
            int a0 = base + q * 4;
            int l, p, h, s; level_of(a0, l, p, h, s);
            int hh = h * h;
            const float* cbase = in.p[l] + b * 15 * hh + p;
            const float4* cls = (const float4*)cbase;
            int st = hh >> 2;
            float4 m4 = cls[0];
#pragma unroll
            for (int c = 1; c < 15; c++) {
                float4 v = cls[c * st];
                m4.x = fmaxf(m4.x, v.x); m4.y = fmaxf(m4.y, v.y);
                m4.z = fmaxf(m4.z, v.z); m4.w = fmaxf(m4.w, v.w);
            }
            float4 sc;
            sc.x = 1.0f / (1.0f + expf(-m4.x));
            sc.y = 1.0f / (1.0f + expf(-m4.y));
            sc.z = 1.0f / (1.0f + expf(-m4.z));
            sc.w = 1.0f / (1.0f + expf(-m4.w));
            *(float4*)&g_score[b * NA + a0] = sc;
            kb[q * 4 + 0] = __float_as_uint(sc.x);
            kb[q * 4 + 1] = __float_as_uint(sc.y);
            kb[q * 4 + 2] = __float_as_uint(sc.z);
            kb[q * 4 + 3] = __float_as_uint(sc.w);
            // hot-argmax for the rare prelist anchors (data is in L1)
#pragma unroll
            for (int comp = 0; comp < 4; comp++) {
                if (kb[q * 4 + comp] >= PRE_BITS) {
                    const float* cp = cbase + comp;
                    float best = cp[0]; int bc = 0;
#pragma unroll
                    for (int c = 1; c < 15; c++) {
                        float v = cp[c * hh];
                        if (v > best) { best = v; bc = c; }
                    }
                    g_clsArg[b * NA + a0 + comp] = (unsigned char)bc;
                }
            }
        }
#pragma unroll
        for (int q = 0; q < 8; q++) cntP += (kb[q] >= PRE_BITS);
    }
    int inc = cntP;
#pragma unroll
    for (int d = 1; d < 32; d <<= 1) {
        int t = __shfl_up_sync(0xffffffffu, inc, d);
        if (lane >= d) inc += t;
    }
    if (lane == 31) wtot[wd] = inc;
    __syncthreads();
    if (tid == 0) {
        int tot = 0;
#pragma unroll
        for (int w = 0; w < 8; w++) { int t = wtot[w]; wtot[w] = tot; tot += t; }
        sBase = tot ? atomicAdd(&g_pcnt[b], tot) : 0;
    }
    __syncthreads();
    if (act && cntP) {
        int off = sBase + wtot[wd] + (inc - cntP);
#pragma unroll
        for (int q = 0; q < 8; q++) {
            if (kb[q] >= PRE_BITS) {
                if (off < PRE_CAP)
                    g_pre[b * PRE_CAP + off] = ((unsigned long long)kb[q] << 32) | (unsigned)(base + q);
                else
                    g_pover[b] = 1;
                off++;
            }
        }
    }
}

// ---------------- threshold finder over a shared histogram ----------------
__device__ __forceinline__ void find_thresh(const int* h, int nbins, int target,
                                            int* partial, int* res, int tid,
                                            int& T, int& acc) {
    int spb = nbins >> 8;
    if (tid < 256) { int s = 0; for (int i = 0; i < spb; i++) s += h[tid * spb + i]; partial[tid] = s; }
    __syncthreads();
    if (tid == 0) {
        int a = 0, TT = 0;
        for (int seg = 255; seg >= 0; seg--) {
            int ps = partial[seg];
            if (a + ps >= target) {
                for (int bin = seg * spb + spb - 1;; bin--) {
                    int hc = h[bin];
                    if (a + hc >= target) { TT = bin; break; }
                    a += hc;
                }
                break;
            }
            a += ps;
        }
        res[0] = TT; res[1] = a;
    }
    __syncthreads();
    T = res[0]; acc = res[1];
}

// ---------------- ballot-aggregated emit into shared cand ----------------
__device__ __forceinline__ void emit_sh(bool em, unsigned k, unsigned a,
                                        unsigned long long* cand, int* sCnt, int lane) {
    unsigned mv = __ballot_sync(0xffffffffu, em);
    if (mv) {
        int ldr = __ffs(mv) - 1;
        int pos = 0;
        if (lane == ldr) pos = atomicAdd(sCnt, __popc(mv));
        pos = __shfl_sync(0xffffffffu, pos, ldr);
        if (em) {
            int o = pos + __popc(mv & ((1u << lane) - 1));
            if (o < 1024)
                cand[o] = ((unsigned long long)(~k) << 32) | a;  // asc sort = desc score, asc idx
        }
    }
}

// ---------------- kernel 2: select + hybrid shuffle/shared bitonic sort (per batch) ----------------
__global__ void __launch_bounds__(1024) topk_kernel() {
    __shared__ int h[4096];
    __shared__ int partial[256];
    __shared__ int res[2];
    __shared__ int h3[256];
    __shared__ int sCnt, sHi;
    __shared__ unsigned long long cand[1024];
    int b = blockIdx.x, tid = threadIdx.x, lane = tid & 31;

    int pcnt = min(g_pcnt[b], PRE_CAP);
    bool usable = (pcnt >= 1000) && (g_pover[b] == 0);
    const unsigned long long* pre = g_pre + b * PRE_CAP;
    const float* sc = g_score + b * NA;

    for (int i = tid; i < 4096; i += 1024) h[i] = 0;
    if (tid < 256) h3[tid] = 0;
    if (tid == 0) { sCnt = 0; sHi = 0; }
    __syncthreads();

    // ---- stage 0: determine T1 / acc1 ----
    int T1, acc1;
    if (usable) {
        int c = 0;
        for (int i = tid; i < pcnt; i += 1024)
            c += ((unsigned)(pre[i] >> 32) >= 0x3F800000u);
#pragma unroll
        for (int d = 16; d > 0; d >>= 1) c += __shfl_down_sync(0xffffffffu, c, d);
        if (lane == 0 && c) atomicAdd(&sHi, c);
    }
    __syncthreads();
    if (usable && sHi < 1000) {
        T1 = 0x3F7; acc1 = sHi;
    } else {
        usable = false;
        for (int it = 0; it < 48; it++) {
            int i = it * 1024 + tid;
            bool v = i < NA;
            unsigned bal = __ballot_sync(0xffffffffu, v);
            if (v) {
                int bin = (int)(__float_as_uint(sc[i]) >> 20);
                unsigned mm = __match_any_sync(bal, bin);
                if (lane == (int)(__ffs(mm) - 1)) atomicAdd(&h[bin], __popc(mm));
            }
        }
        __syncthreads();
        find_thresh(h, 4096, 1000, partial, res, tid, T1, acc1);
        __syncthreads();
        for (int i = tid; i < 4096; i += 1024) h[i] = 0;
        __syncthreads();
    }

    int nIt = usable ? ((pcnt + 1023) >> 10) : 48;

    // ---- stage 1: emit bin>T1 ; hist mid-12 for bin==T1 ----
    for (int it = 0; it < nIt; it++) {
        int i = it * 1024 + tid;
        unsigned k = 0, a = 0; bool em = false;
        if (usable) {
            if (i < pcnt) { unsigned long long v = pre[i]; k = (unsigned)(v >> 32); a = (unsigned)v; }
        } else if (i < NA) { k = __float_as_uint(sc[i]); a = (unsigned)i; }
        if (k) {
            int bin = (int)(k >> 20);
            if (bin > T1) em = true;
            else if (bin == T1) atomicAdd(&h[(k >> 8) & 0xFFF], 1);
        }
        emit_sh(em, k, a, cand, &sCnt, lane);
    }
    __syncthreads();
    int T2, acc2;
    find_thresh(h, 4096, 1000 - acc1, partial, res, tid, T2, acc2);
    __syncthreads();

    // ---- stage 2: low-byte hist for bin==T1 && mid==T2 ----
    for (int it = 0; it < nIt; it++) {
        int i = it * 1024 + tid;
        unsigned k = 0;
        if (usable) { if (i < pcnt) k = (unsigned)(pre[i] >> 32); }
        else if (i < NA) k = __float_as_uint(sc[i]);
        if (k && (int)(k >> 20) == T1 && (int)((k >> 8) & 0xFFF) == T2)
            atomicAdd(&h3[k & 0xFF], 1);
    }
    __syncthreads();
    if (tid == 0) {
        int tg = 1000 - acc1 - acc2, a = 0, T = 0;
        for (int bin = 255;; bin--) {
            int hc = h3[bin];
            if (a + hc >= tg) { T = bin; break; }
            a += hc;
        }
        res[0] = T;
    }
    __syncthreads();
    int T3 = res[0];

    // ---- stage 3: emit remainder ----
    for (int it = 0; it < nIt; it++) {
        int i = it * 1024 + tid;
        unsigned k = 0, a = 0; bool em = false;
        if (usable) {
            if (i < pcnt) { unsigned long long v = pre[i]; k = (unsigned)(v >> 32); a = (unsigned)v; }
        } else if (i < NA) { k = __float_as_uint(sc[i]); a = (unsigned)i; }
        if (k && (int)(k >> 20) == T1) {
            int mid = (int)((k >> 8) & 0xFFF);
            em = (mid > T2) || (mid == T2 && (int)(k & 0xFF) >= T3);
        }
        emit_sh(em, k, a, cand, &sCnt, lane);
    }
    __syncthreads();
    int c = min(sCnt, 1024);
    if (tid >= c) cand[tid] = 0xFFFFFFFFFFFFFFFFULL;
    __syncthreads();

    // ---- stage 4: hybrid bitonic sort (register value; shuffle intra-warp, shared cross-warp) ----
    unsigned long long val = cand[tid];
#pragma unroll
    for (int k2 = 2; k2 <= 1024; k2 <<= 1) {
        bool asc = ((tid & k2) == 0);
        for (int s2 = k2 >> 1; s2 >= 32; s2 >>= 1) {
            cand[tid] = val;
            __syncthreads();
            unsigned long long ov = cand[tid ^ s2];
            bool low = ((tid & s2) == 0);
            bool takeMin = (low == asc);
            val = (takeMin == (val < ov)) ? val : ov;
            __syncthreads();
        }
#pragma unroll
        for (int s2 = (k2 > 32 ? 16 : (k2 >> 1)); s2 >= 1; s2 >>= 1) {
            unsigned long long ov = __shfl_xor_sync(0xffffffffu, val, s2);
            bool low = ((tid & s2) == 0);
            bool takeMin = (low == asc);
            val = (takeMin == (val < ov)) ? val : ov;
        }
    }
    g_cand[b * 1024 + tid] = val;
    if (tid == 0) { g_cnt[b] = c; g_usable[b] = usable ? 1 : 0; }
}

// ---------------- kernel 3: winner decode — one WARP per winner; also re-arms counters ----------------
__global__ void __launch_bounds__(256) decode_kernel(Ptrs in) {
    int b = blockIdx.y;
    if (blockIdx.x == 0 && threadIdx.x == 0) { g_pcnt[b] = 0; g_pover[b] = 0; }  // re-arm for next replay
    int w = blockIdx.x * 8 + (threadIdx.x >> 5);   // winner slot 0..1023
    int lane = threadIdx.x & 31;
    int o = b * 1024 + w;
    int cnt = g_cnt[b];
    int usab = g_usable[b];

    if (w < 1000 && w < cnt) {
        unsigned long long v = g_cand[o];
        int a = (int)(unsigned)(v & 0xFFFFFFFFu);
        float score = __uint_as_float(~(unsigned)(v >> 32));

        int l, p, h2, s; level_of(a, l, p, h2, s);
        int hh = h2 * h2;
        const float* reg = in.p[5 + l]  + b * 5  * hh + p;
        const float* tcp = in.p[10 + l] + b * 18 * hh + p;
        const float* trp = in.p[15 + l] + b * hh + p;

        float v2 = (lane < 18) ? tcp[lane * hh] : -1e30f;
        int   i2 = lane;
        float rq = (lane < 4) ? reg[lane * hh] : ((lane == 4) ? trp[0] : 0.f);
        int clsA = 0;
        if (usab) {
            if (lane == 5) clsA = (int)g_clsArg[b * NA + a];
        } else {
            // fallback: compute cls argmax lane-parallel
            const float* cls = in.p[l] + b * 15 * hh + p;
            float v1 = (lane < 15) ? cls[lane * hh] : -1e30f;
            int   i1 = lane;
#pragma unroll
            for (int d = 16; d > 0; d >>= 1) {
                float ov = __shfl_down_sync(0xffffffffu, v1, d);
                int   oi = __shfl_down_sync(0xffffffffu, i1, d);
                if (ov > v1 || (ov == v1 && oi < i1)) { v1 = ov; i1 = oi; }
            }
            if (lane == 0) clsA = i1;
            clsA = __shfl_sync(0xffffffffu, clsA, 0);
            if (lane == 5) ; // keep uniform
        }
#pragma unroll
        for (int d = 16; d > 0; d >>= 1) {
            float ov2 = __shfl_down_sync(0xffffffffu, v2, d);
            int   oi2 = __shfl_down_sync(0xffffffffu, i2, d);
            if (ov2 > v2 || (ov2 == v2 && oi2 < i2)) { v2 = ov2; i2 = oi2; }
        }
        float r0v = __shfl_sync(0xffffffffu, rq, 0);
        float r1v = __shfl_sync(0xffffffffu, rq, 1);
        float r2v = __shfl_sync(0xffffffffu, rq, 2);
        float r3v = __shfl_sync(0xffffffffu, rq, 3);
        float trv = __shfl_sync(0xffffffffu, rq, 4);
        if (usab) clsA = __shfl_sync(0xffffffffu, clsA, 5);

        if (lane == 0) {
            float theta = (float)(i2 + 1) * 10.0f + trv;
            float fs = (float)s;
            int col = p % h2, row = p / h2;
            float x = (float)col * fs + (float)(s / 2);
            float y = (float)row * fs + (float)(s / 2);

            g_topScore[o] = score;
            g_topCls[o]   = (float)(clsA + 1);
            g_topTheta[o] = theta;
            g_topBox[o * 4 + 0] = x - r0v * fs;
            g_topBox[o * 4 + 1] = y - r1v * fs;
            g_topBox[o * 4 + 2] = x + r2v * fs;
            g_topBox[o * 4 + 3] = y + r3v * fs;
        }
    } else if (lane == 0) {
        g_topScore[o] = -1e30f;
        g_topCls[o] = 0.f; g_topTheta[o] = 0.f;
        g_topBox[o * 4 + 0] = 0.f; g_topBox[o * 4 + 1] = 0.f;
        g_topBox[o * 4 + 2] = 0.f; g_topBox[o * 4 + 3] = 0.f;
    }
}

// ---------------- kernel 4: IoU bit-masks (slimmed inner loop) ----------------
__global__ void __launch_bounds__(1024) mask_kernel() {
    int b = blockIdx.y, g = blockIdx.x, j = threadIdx.x;
    int wid = j >> 5, lane = j & 31;
    __shared__ float ib[32][5];     // x1,y1,x2,y2,area (stride 5: conflict-free broadcast)
    if (j < 32) {
        float x1 = g_topBox[(b * 1024 + g * 32 + j) * 4 + 0];
        float y1 = g_topBox[(b * 1024 + g * 32 + j) * 4 + 1];
        float x2 = g_topBox[(b * 1024 + g * 32 + j) * 4 + 2];
        float y2 = g_topBox[(b * 1024 + g * 32 + j) * 4 + 3];
        ib[j][0] = x1; ib[j][1] = y1; ib[j][2] = x2; ib[j][3] = y2;
        ib[j][4] = fmaxf(x2 - x1, 0.f) * fmaxf(y2 - y1, 0.f);
    }
    __syncthreads();

    if (wid < g) return;   // dead region: scan never reads these words

    float x1 = g_topBox[(b * 1024 + j) * 4 + 0];
    float y1 = g_topBox[(b * 1024 + j) * 4 + 1];
    float x2 = g_topBox[(b * 1024 + j) * 4 + 2];
    float y2 = g_topBox[(b * 1024 + j) * 4 + 3];
    float area = fmaxf(x2 - x1, 0.f) * fmaxf(y2 - y1, 0.f);

    if (wid > g) {
        unsigned w = 0;
#pragma unroll
        for (int bb = 0; bb < 32; bb++) {
            float iw = fmaxf(fminf(x2, ib[bb][2]) - fmaxf(x1, ib[bb][0]), 0.f);
            float ih = fmaxf(fminf(y2, ib[bb][3]) - fmaxf(y1, ib[bb][1]), 0.f);
            float inter = iw * ih;
            float uni = fmaxf(area + ib[bb][4] - inter, 1e-8f);
            w |= ((unsigned)(inter > 0.3f * uni)) << bb;
        }
        g_W[(b * 32 + g) * 1024 + j] = w;
    } else {
        unsigned w = 0;
#pragma unroll
        for (int bb = 0; bb < 32; bb++) {
            float iw = fmaxf(fminf(x2, ib[bb][2]) - fmaxf(x1, ib[bb][0]), 0.f);
            float ih = fmaxf(fminf(y2, ib[bb][3]) - fmaxf(y1, ib[bb][1]), 0.f);
            float inter = iw * ih;
            float uni = fmaxf(area + ib[bb][4] - inter, 1e-8f);
            bool pred = (inter > 0.3f * uni) && (bb < lane);
            w |= ((unsigned)pred) << bb;
        }
        unsigned u = 0;
#pragma unroll
        for (int i = 0; i < 32; i++) {
            unsigned t = __ballot_sync(0xffffffffu, (w >> i) & 1u);
            if (lane == i) u = t;
        }
        g_U[b * 1024 + g * 32 + lane] = u;
    }
}

// ---------------- kernel 5: barrier-free pipelined greedy scan + output ----------------
__global__ void __launch_bounds__(1024) scan_kernel(float* __restrict__ out) {
    int b = blockIdx.x, j = threadIdx.x;
    int lane = j & 31, wid = j >> 5;
    __shared__ unsigned su[1024];
    __shared__ unsigned long long sm64[32];

    float score = g_topScore[b * 1024 + j];
    bool alive = (j < 1000) && (score >= 0.05f);

    unsigned su_own = g_U[b * 1024 + j];
    su[j] = su_own;
    if (j < 32) sm64[j] = 0ULL;
    unsigned nzm = __ballot_sync(0xffffffffu, su_own != 0u);
    __syncthreads();

    const unsigned* Wb = g_W + b * 32 * 1024;
    for (int g = 0; g < wid; g++) {
        unsigned wv = Wb[g * 1024 + j];
        unsigned long long v;
        do { v = *(volatile const unsigned long long*)&sm64[g]; } while (!(v >> 32));
        unsigned mg = (unsigned)v;
        alive = alive && ((wv & mg) == 0u);
    }
    unsigned m = __ballot_sync(0xffffffffu, alive);
    if (lane == 0) {
        unsigned todo = nzm & m;
        while (todo) {
            int bb = __ffs(todo) - 1;
            m &= ~su[wid * 32 + bb];
            todo &= todo - 1;
            todo &= m;
        }
        *(volatile unsigned long long*)&sm64[wid] = (1ULL << 32) | (unsigned long long)m;
    }
    m = __shfl_sync(0xffffffffu, m, 0);
    alive = (m >> lane) & 1u;

    if (j < 1000) {
        float k = alive ? 1.0f : 0.0f;
        int o = b * 1024 + j;
        out[b * 1000 + j] = score * k;
        out[16000 + b * 1000 + j] = k * g_topCls[o];
        int base = 32000 + (b * 1000 + j) * 5;
        out[base + 0] = k * g_topBox[o * 4 + 0];
        out[base + 1] = k * g_topBox[o * 4 + 1];
        out[base + 2] = k * g_topBox[o * 4 + 2];
        out[base + 3] = k * g_topBox[o * 4 + 3];
        out[base + 4] = k * g_topTheta[o];
    }
}

// ---------------- launch ----------------
extern "C" void kernel_launch(void* const* d_in, const int* in_sizes, int n_in,
                              void* d_out, int out_size) {
    Ptrs P;
    for (int i = 0; i < 20; i++) P.p[i] = (const float*)d_in[i];

    score_pre_kernel<<<dim3(24, NB), 256>>>(P);
    topk_kernel<<<NB, 1024>>>();
    decode_kernel<<<dim3(128, NB), 256>>>(P);
    mask_kernel<<<dim3(32, NB), 1024>>>();
    scan_kernel<<<NB, 1024>>>((float*)d_out);
}

// round 17
// speedup vs baseline: 1.0967x; 1.0645x over previous
#include <cuda_runtime.h>
#include <cuda_bf16.h>

#define NB 16
#define NA 49104
#define PRE_CAP 6144
#define PRE_BITS 0x3F700000u   // 0.9375f ; all prelist items have (bits>>20) >= 0x3F7

// ---------------- scratch (device globals; zero-initialized at module load) ----------------
__device__ float g_score[NB * NA];
__device__ unsigned char g_clsArg[NB * NA];   // written only for prelist anchors
__device__ int   g_pcnt[NB];
__device__ int   g_pover[NB];
__device__ int   g_cnt[NB];
__device__ int   g_usable[NB];
__device__ unsigned long long g_pre[NB * PRE_CAP];
__device__ unsigned long long g_cand[NB * 1024];

__device__ float g_topScore[NB * 1024];
__device__ float g_topCls[NB * 1024];
__device__ float g_topTheta[NB * 1024];
__device__ float g_topBox[NB * 1024 * 4];

__device__ unsigned g_W[NB * 32 * 1024];  // [b][g][j] : bit i = iou(i,j)>thr  (only wid>g region)
__device__ unsigned g_U[NB * 1024];       // [b][g*32+i] : intra-group row (suppressor i)

struct Ptrs { const float* p[20]; };

__device__ __forceinline__ void level_of(int a, int& l, int& p, int& h, int& s) {
    if (a < 36864)      { l = 0; p = a;         h = 192; s = 8;   }
    else if (a < 46080) { l = 1; p = a - 36864; h = 96;  s = 16;  }
    else if (a < 48384) { l = 2; p = a - 46080; h = 48;  s = 32;  }
    else if (a < 48960) { l = 3; p = a - 48384; h = 24;  s = 64;  }
    else                { l = 4; p = a - 48960; h = 12;  s = 128; }
}

// ---------------- kernel 1: scores (fmaxf only) + prelist + hot-argmax for prelist anchors ----------------
__global__ void __launch_bounds__(256) score_pre_kernel(Ptrs in) {
    __shared__ int wtot[8];
    __shared__ int sBase;
    int b = blockIdx.y, bx = blockIdx.x, tid = threadIdx.x;
    int lane = tid & 31, wd = tid >> 5;

    int base = bx * 2048 + tid * 8;   // 8 anchors / thread; 4-groups never cross level bound
    unsigned kb[8];
    int cntP = 0;
    bool act = base < NA;
    if (act) {
#pragma unroll
        for (int q = 0; q < 2; q++) {
            int a0 = base + q * 4;
            int l, p, h, s; level_of(a0, l, p, h, s);
            int hh = h * h;
            const float* cbase = in.p[l] + b * 15 * hh + p;
            const float4* cls = (const float4*)cbase;
            int st = hh >> 2;
            float4 m4 = cls[0];
#pragma unroll
            for (int c = 1; c < 15; c++) {
                float4 v = cls[c * st];
                m4.x = fmaxf(m4.x, v.x); m4.y = fmaxf(m4.y, v.y);
                m4.z = fmaxf(m4.z, v.z); m4.w = fmaxf(m4.w, v.w);
            }
            float4 sc;
            sc.x = 1.0f / (1.0f + expf(-m4.x));
            sc.y = 1.0f / (1.0f + expf(-m4.y));
            sc.z = 1.0f / (1.0f + expf(-m4.z));
            sc.w = 1.0f / (1.0f + expf(-m4.w));
            *(float4*)&g_score[b * NA + a0] = sc;
            kb[q * 4 + 0] = __float_as_uint(sc.x);
            kb[q * 4 + 1] = __float_as_uint(sc.y);
            kb[q * 4 + 2] = __float_as_uint(sc.z);
            kb[q * 4 + 3] = __float_as_uint(sc.w);
            // hot-argmax for the rare prelist anchors (data is in L1)
#pragma unroll
            for (int comp = 0; comp < 4; comp++) {
                if (kb[q * 4 + comp] >= PRE_BITS) {
                    const float* cp = cbase + comp;
                    float best = cp[0]; int bc = 0;
#pragma unroll
                    for (int c = 1; c < 15; c++) {
                        float v = cp[c * hh];
                        if (v > best) { best = v; bc = c; }
                    }
                    g_clsArg[b * NA + a0 + comp] = (unsigned char)bc;
                }
            }
        }
#pragma unroll
        for (int q = 0; q < 8; q++) cntP += (kb[q] >= PRE_BITS);
    }
    int inc = cntP;
#pragma unroll
    for (int d = 1; d < 32; d <<= 1) {
        int t = __shfl_up_sync(0xffffffffu, inc, d);
        if (lane >= d) inc += t;
    }
    if (lane == 31) wtot[wd] = inc;
    __syncthreads();
    if (tid == 0) {
        int tot = 0;
#pragma unroll
        for (int w = 0; w < 8; w++) { int t = wtot[w]; wtot[w] = tot; tot += t; }
        sBase = tot ? atomicAdd(&g_pcnt[b], tot) : 0;
    }
    __syncthreads();
    if (act && cntP) {
        int off = sBase + wtot[wd] + (inc - cntP);
#pragma unroll
        for (int q = 0; q < 8; q++) {
            if (kb[q] >= PRE_BITS) {
                if (off < PRE_CAP)
                    g_pre[b * PRE_CAP + off] = ((unsigned long long)kb[q] << 32) | (unsigned)(base + q);
                else
                    g_pover[b] = 1;
                off++;
            }
        }
    }
}

// ---------------- threshold finder over a shared histogram ----------------
__device__ __forceinline__ void find_thresh(const int* h, int nbins, int target,
                                            int* partial, int* res, int tid,
                                            int& T, int& acc) {
    int spb = nbins >> 8;
    if (tid < 256) { int s = 0; for (int i = 0; i < spb; i++) s += h[tid * spb + i]; partial[tid] = s; }
    __syncthreads();
    if (tid == 0) {
        int a = 0, TT = 0;
        for (int seg = 255; seg >= 0; seg--) {
            int ps = partial[seg];
            if (a + ps >= target) {
                for (int bin = seg * spb + spb - 1;; bin--) {
                    int hc = h[bin];
                    if (a + hc >= target) { TT = bin; break; }
                    a += hc;
                }
                break;
            }
            a += ps;
        }
        res[0] = TT; res[1] = a;
    }
    __syncthreads();
    T = res[0]; acc = res[1];
}

// ---------------- ballot-aggregated emit into shared cand ----------------
__device__ __forceinline__ void emit_sh(bool em, unsigned k, unsigned a,
                                        unsigned long long* cand, int* sCnt, int lane) {
    unsigned mv = __ballot_sync(0xffffffffu, em);
    if (mv) {
        int ldr = __ffs(mv) - 1;
        int pos = 0;
        if (lane == ldr) pos = atomicAdd(sCnt, __popc(mv));
        pos = __shfl_sync(0xffffffffu, pos, ldr);
        if (em) {
            int o = pos + __popc(mv & ((1u << lane) - 1));
            if (o < 1024)
                cand[o] = ((unsigned long long)(~k) << 32) | a;  // asc sort = desc score, asc idx
        }
    }
}

// ---------------- kernel 2: select + hybrid shuffle/shared bitonic sort (per batch) ----------------
__global__ void __launch_bounds__(1024) topk_kernel() {
    __shared__ int h[4096];
    __shared__ int partial[256];
    __shared__ int res[2];
    __shared__ int h3[256];
    __shared__ int sCnt, sHi;
    __shared__ unsigned long long cand[1024];
    int b = blockIdx.x, tid = threadIdx.x, lane = tid & 31;

    int pcnt = min(g_pcnt[b], PRE_CAP);
    bool usable = (pcnt >= 1000) && (g_pover[b] == 0);
    const unsigned long long* pre = g_pre + b * PRE_CAP;
    const float* sc = g_score + b * NA;

    for (int i = tid; i < 4096; i += 1024) h[i] = 0;
    if (tid < 256) h3[tid] = 0;
    if (tid == 0) { sCnt = 0; sHi = 0; }
    __syncthreads();

    // ---- stage 0: determine T1 / acc1 ----
    int T1, acc1;
    if (usable) {
        int c = 0;
        for (int i = tid; i < pcnt; i += 1024)
            c += ((unsigned)(pre[i] >> 32) >= 0x3F800000u);
#pragma unroll
        for (int d = 16; d > 0; d >>= 1) c += __shfl_down_sync(0xffffffffu, c, d);
        if (lane == 0 && c) atomicAdd(&sHi, c);
    }
    __syncthreads();
    if (usable && sHi < 1000) {
        T1 = 0x3F7; acc1 = sHi;
    } else {
        usable = false;
        for (int it = 0; it < 48; it++) {
            int i = it * 1024 + tid;
            bool v = i < NA;
            unsigned bal = __ballot_sync(0xffffffffu, v);
            if (v) {
                int bin = (int)(__float_as_uint(sc[i]) >> 20);
                unsigned mm = __match_any_sync(bal, bin);
                if (lane == (int)(__ffs(mm) - 1)) atomicAdd(&h[bin], __popc(mm));
            }
        }
        __syncthreads();
        find_thresh(h, 4096, 1000, partial, res, tid, T1, acc1);
        __syncthreads();
        for (int i = tid; i < 4096; i += 1024) h[i] = 0;
        __syncthreads();
    }

    int nIt = usable ? ((pcnt + 1023) >> 10) : 48;

    // ---- stage 1: emit bin>T1 ; hist mid-12 for bin==T1 ----
    for (int it = 0; it < nIt; it++) {
        int i = it * 1024 + tid;
        unsigned k = 0, a = 0; bool em = false;
        if (usable) {
            if (i < pcnt) { unsigned long long v = pre[i]; k = (unsigned)(v >> 32); a = (unsigned)v; }
        } else if (i < NA) { k = __float_as_uint(sc[i]); a = (unsigned)i; }
        if (k) {
            int bin = (int)(k >> 20);
            if (bin > T1) em = true;
            else if (bin == T1) atomicAdd(&h[(k >> 8) & 0xFFF], 1);
        }
        emit_sh(em, k, a, cand, &sCnt, lane);
    }
    __syncthreads();
    int T2, acc2;
    find_thresh(h, 4096, 1000 - acc1, partial, res, tid, T2, acc2);
    __syncthreads();

    // ---- stage 2: low-byte hist for bin==T1 && mid==T2 ----
    for (int it = 0; it < nIt; it++) {
        int i = it * 1024 + tid;
        unsigned k = 0;
        if (usable) { if (i < pcnt) k = (unsigned)(pre[i] >> 32); }
        else if (i < NA) k = __float_as_uint(sc[i]);
        if (k && (int)(k >> 20) == T1 && (int)((k >> 8) & 0xFFF) == T2)
            atomicAdd(&h3[k & 0xFF], 1);
    }
    __syncthreads();
    if (tid == 0) {
        int tg = 1000 - acc1 - acc2, a = 0, T = 0;
        for (int bin = 255;; bin--) {
            int hc = h3[bin];
            if (a + hc >= tg) { T = bin; break; }
            a += hc;
        }
        res[0] = T;
    }
    __syncthreads();
    int T3 = res[0];

    // ---- stage 3: emit remainder ----
    for (int it = 0; it < nIt; it++) {
        int i = it * 1024 + tid;
        unsigned k = 0, a = 0; bool em = false;
        if (usable) {
            if (i < pcnt) { unsigned long long v = pre[i]; k = (unsigned)(v >> 32); a = (unsigned)v; }
        } else if (i < NA) { k = __float_as_uint(sc[i]); a = (unsigned)i; }
        if (k && (int)(k >> 20) == T1) {
            int mid = (int)((k >> 8) & 0xFFF);
            em = (mid > T2) || (mid == T2 && (int)(k & 0xFF) >= T3);
        }
        emit_sh(em, k, a, cand, &sCnt, lane);
    }
    __syncthreads();
    int c = min(sCnt, 1024);
    if (tid >= c) cand[tid] = 0xFFFFFFFFFFFFFFFFULL;
    __syncthreads();

    // ---- stage 4: hybrid bitonic sort (register value; shuffle intra-warp, shared cross-warp) ----
    unsigned long long val = cand[tid];
#pragma unroll
    for (int k2 = 2; k2 <= 1024; k2 <<= 1) {
        bool asc = ((tid & k2) == 0);
        for (int s2 = k2 >> 1; s2 >= 32; s2 >>= 1) {
            cand[tid] = val;
            __syncthreads();
            unsigned long long ov = cand[tid ^ s2];
            bool low = ((tid & s2) == 0);
            bool takeMin = (low == asc);
            val = (takeMin == (val < ov)) ? val : ov;
            __syncthreads();
        }
#pragma unroll
        for (int s2 = (k2 > 32 ? 16 : (k2 >> 1)); s2 >= 1; s2 >>= 1) {
            unsigned long long ov = __shfl_xor_sync(0xffffffffu, val, s2);
            bool low = ((tid & s2) == 0);
            bool takeMin = (low == asc);
            val = (takeMin == (val < ov)) ? val : ov;
        }
    }
    g_cand[b * 1024 + tid] = val;
    if (tid == 0) { g_cnt[b] = c; g_usable[b] = usable ? 1 : 0; }
}

// ---------------- kernel 3: winner decode — one WARP per winner; also re-arms counters ----------------
__global__ void __launch_bounds__(256) decode_kernel(Ptrs in) {
    int b = blockIdx.y;
    if (blockIdx.x == 0 && threadIdx.x == 0) { g_pcnt[b] = 0; g_pover[b] = 0; }  // re-arm for next replay
    int w = blockIdx.x * 8 + (threadIdx.x >> 5);   // winner slot 0..1023
    int lane = threadIdx.x & 31;
    int o = b * 1024 + w;
    int cnt = g_cnt[b];
    int usab = g_usable[b];

    if (w < 1000 && w < cnt) {
        unsigned long long v = g_cand[o];
        int a = (int)(unsigned)(v & 0xFFFFFFFFu);
        float score = __uint_as_float(~(unsigned)(v >> 32));

        int l, p, h2, s; level_of(a, l, p, h2, s);
        int hh = h2 * h2;
        const float* reg = in.p[5 + l]  + b * 5  * hh + p;
        const float* tcp = in.p[10 + l] + b * 18 * hh + p;
        const float* trp = in.p[15 + l] + b * hh + p;

        float v2 = (lane < 18) ? tcp[lane * hh] : -1e30f;
        int   i2 = lane;
        float rq = (lane < 4) ? reg[lane * hh] : ((lane == 4) ? trp[0] : 0.f);
        int clsA = 0;
        if (usab) {
            if (lane == 5) clsA = (int)g_clsArg[b * NA + a];
        } else {
            const float* cls = in.p[l] + b * 15 * hh + p;
            float v1 = (lane < 15) ? cls[lane * hh] : -1e30f;
            int   i1 = lane;
#pragma unroll
            for (int d = 16; d > 0; d >>= 1) {
                float ov = __shfl_down_sync(0xffffffffu, v1, d);
                int   oi = __shfl_down_sync(0xffffffffu, i1, d);
                if (ov > v1 || (ov == v1 && oi < i1)) { v1 = ov; i1 = oi; }
            }
            if (lane == 0) clsA = i1;
            clsA = __shfl_sync(0xffffffffu, clsA, 0);
        }
#pragma unroll
        for (int d = 16; d > 0; d >>= 1) {
            float ov2 = __shfl_down_sync(0xffffffffu, v2, d);
            int   oi2 = __shfl_down_sync(0xffffffffu, i2, d);
            if (ov2 > v2 || (ov2 == v2 && oi2 < i2)) { v2 = ov2; i2 = oi2; }
        }
        float r0v = __shfl_sync(0xffffffffu, rq, 0);
        float r1v = __shfl_sync(0xffffffffu, rq, 1);
        float r2v = __shfl_sync(0xffffffffu, rq, 2);
        float r3v = __shfl_sync(0xffffffffu, rq, 3);
        float trv = __shfl_sync(0xffffffffu, rq, 4);
        if (usab) clsA = __shfl_sync(0xffffffffu, clsA, 5);

        if (lane == 0) {
            float theta = (float)(i2 + 1) * 10.0f + trv;
            float fs = (float)s;
            int col = p % h2, row = p / h2;
            float x = (float)col * fs + (float)(s / 2);
            float y = (float)row * fs + (float)(s / 2);

            g_topScore[o] = score;
            g_topCls[o]   = (float)(clsA + 1);
            g_topTheta[o] = theta;
            g_topBox[o * 4 + 0] = x - r0v * fs;
            g_topBox[o * 4 + 1] = y - r1v * fs;
            g_topBox[o * 4 + 2] = x + r2v * fs;
            g_topBox[o * 4 + 3] = y + r3v * fs;
        }
    } else if (lane == 0) {
        g_topScore[o] = -1e30f;
        g_topCls[o] = 0.f; g_topTheta[o] = 0.f;
        g_topBox[o * 4 + 0] = 0.f; g_topBox[o * 4 + 1] = 0.f;
        g_topBox[o * 4 + 2] = 0.f; g_topBox[o * 4 + 3] = 0.f;
    }
}

// ---------------- kernel 4: IoU bit-masks — live tiles only, 256-thread blocks ----------------
// grid.x = 80 tiles/batch: chunk c covers j-warps 8c..8c+7; block (c,g) exists iff g <= 8c+7.
// Flat: t<8 -> c=0,g=t ; t<24 -> c=1,g=t-8 ; t<48 -> c=2,g=t-24 ; else c=3,g=t-48.
__global__ void __launch_bounds__(256) mask_kernel() {
    int b = blockIdx.y;
    int t = blockIdx.x;
    int c, g;
    if (t < 8)       { c = 0; g = t; }
    else if (t < 24) { c = 1; g = t - 8; }
    else if (t < 48) { c = 2; g = t - 24; }
    else             { c = 3; g = t - 48; }

    int tid = threadIdx.x;
    int lw = tid >> 5, lane = tid & 31;
    int wid = c * 8 + lw;            // global j-warp id
    int j = wid * 32 + lane;

    __shared__ float ib[32][5];      // x1,y1,x2,y2,area
    if (tid < 32) {
        float4 bx = *(const float4*)&g_topBox[(b * 1024 + g * 32 + tid) * 4];
        ib[tid][0] = bx.x; ib[tid][1] = bx.y; ib[tid][2] = bx.z; ib[tid][3] = bx.w;
        ib[tid][4] = fmaxf(bx.z - bx.x, 0.f) * fmaxf(bx.w - bx.y, 0.f);
    }
    __syncthreads();

    if (wid < g) return;             // partial first chunk only

    float4 jb4 = *(const float4*)&g_topBox[(b * 1024 + j) * 4];
    float x1 = jb4.x, y1 = jb4.y, x2 = jb4.z, y2 = jb4.w;
    float area = fmaxf(x2 - x1, 0.f) * fmaxf(y2 - y1, 0.f);

    if (wid > g) {
        unsigned w = 0;
#pragma unroll
        for (int bb = 0; bb < 32; bb++) {
            float iw = fmaxf(fminf(x2, ib[bb][2]) - fmaxf(x1, ib[bb][0]), 0.f);
            float ih = fmaxf(fminf(y2, ib[bb][3]) - fmaxf(y1, ib[bb][1]), 0.f);
            float inter = iw * ih;
            float uni = fmaxf(area + ib[bb][4] - inter, 1e-8f);
            w |= ((unsigned)(inter > 0.3f * uni)) << bb;
        }
        g_W[(b * 32 + g) * 1024 + j] = w;
    } else {
        unsigned w = 0;
#pragma unroll
        for (int bb = 0; bb < 32; bb++) {
            float iw = fmaxf(fminf(x2, ib[bb][2]) - fmaxf(x1, ib[bb][0]), 0.f);
            float ih = fmaxf(fminf(y2, ib[bb][3]) - fmaxf(y1, ib[bb][1]), 0.f);
            float inter = iw * ih;
            float uni = fmaxf(area + ib[bb][4] - inter, 1e-8f);
            bool pred = (inter > 0.3f * uni) && (bb < lane);
            w |= ((unsigned)pred) << bb;
        }
        unsigned u = 0;
#pragma unroll
        for (int i = 0; i < 32; i++) {
            unsigned tb = __ballot_sync(0xffffffffu, (w >> i) & 1u);
            if (lane == i) u = tb;
        }
        g_U[b * 1024 + g * 32 + lane] = u;
    }
}

// ---------------- kernel 5: barrier-free pipelined greedy scan + output ----------------
__global__ void __launch_bounds__(1024) scan_kernel(float* __restrict__ out) {
    int b = blockIdx.x, j = threadIdx.x;
    int lane = j & 31, wid = j >> 5;
    __shared__ unsigned su[1024];
    __shared__ unsigned long long sm64[32];

    float score = g_topScore[b * 1024 + j];
    bool alive = (j < 1000) && (score >= 0.05f);

    unsigned su_own = g_U[b * 1024 + j];
    su[j] = su_own;
    if (j < 32) sm64[j] = 0ULL;
    unsigned nzm = __ballot_sync(0xffffffffu, su_own != 0u);
    __syncthreads();

    const unsigned* Wb = g_W + b * 32 * 1024;
    for (int g = 0; g < wid; g++) {
        unsigned wv = Wb[g * 1024 + j];
        unsigned long long v;
        do { v = *(volatile const unsigned long long*)&sm64[g]; } while (!(v >> 32));
        unsigned mg = (unsigned)v;
        alive = alive && ((wv & mg) == 0u);
    }
    unsigned m = __ballot_sync(0xffffffffu, alive);
    if (lane == 0) {
        unsigned todo = nzm & m;
        while (todo) {
            int bb = __ffs(todo) - 1;
            m &= ~su[wid * 32 + bb];
            todo &= todo - 1;
            todo &= m;
        }
        *(volatile unsigned long long*)&sm64[wid] = (1ULL << 32) | (unsigned long long)m;
    }
    m = __shfl_sync(0xffffffffu, m, 0);
    alive = (m >> lane) & 1u;

    if (j < 1000) {
        float k = alive ? 1.0f : 0.0f;
        int o = b * 1024 + j;
        out[b * 1000 + j] = score * k;
        out[16000 + b * 1000 + j] = k * g_topCls[o];
        int base = 32000 + (b * 1000 + j) * 5;
        out[base + 0] = k * g_topBox[o * 4 + 0];
        out[base + 1] = k * g_topBox[o * 4 + 1];
        out[base + 2] = k * g_topBox[o * 4 + 2];
        out[base + 3] = k * g_topBox[o * 4 + 3];
        out[base + 4] = k * g_topTheta[o];
    }
}

// ---------------- launch ----------------
extern "C" void kernel_launch(void* const* d_in, const int* in_sizes, int n_in,
                              void* d_out, int out_size) {
    Ptrs P;
    for (int i = 0; i < 20; i++) P.p[i] = (const float*)d_in[i];

    score_pre_kernel<<<dim3(24, NB), 256>>>(P);
    topk_kernel<<<NB, 1024>>>();
    decode_kernel<<<dim3(128, NB), 256>>>(P);
    mask_kernel<<<dim3(80, NB), 256>>>();
    scan_kernel<<<NB, 1024>>>((float*)d_out);
}